// round 8
// baseline (speedup 1.0000x reference)
#include <cuda_runtime.h>

// NonMaxSuppression: 3x3 local max + thr 0.6 + 10px border on (16,1,1536,1536) f32.
// Output: float32 [2, K]; row 0 = y, row 1 = x, in row-major (b,y,x) nonzero order.
// (Reference emits int32 indices; harness canonicalizes output dtype to f32.)
//
//   zf     : zero-fill output (poison safety).
//   countk : one warp per image row -> ballot candidate words to g_mask (L2-resident)
//            + per-row candidate count.
//   scank  : chunked register scan, 24 rows/thread, warp-shuffle block scan.
//   emitk  : one warp per image row -> decode g_mask words, ballot-rank ordered
//            emission at g_rowoff[row]. No atomics; fully deterministic.

#define Bn 16
#define Hn 1536
#define Wn 1536
#define WPR 48                      // 32-px words per row
#define NR (Bn * Hn)                // 24576 global rows
#define RPB 8                       // warps (rows) per block
#define TA 256
#define RPT 24                      // rows per scan thread (NR / 1024)
#define NEGF (-3.402823466e38f)     // -FLT_MAX; input values are in [0,1)

__device__ unsigned g_mask[(size_t)NR * WPR];   // 4.7 MB candidate bitmask
__device__ int g_rowcnt[NR];
__device__ int g_rowoff[NR];

// Candidate word for 32 pixels [wx*32, wx*32+32) of interior row y (10 <= y <= H-11).
__device__ __forceinline__ unsigned row_word(const float* __restrict__ img,
                                             int y, int wx, int lane) {
    const int x = wx * 32 + lane;
    const size_t o = (size_t)y * Wn + x;
    const float up  = img[o - Wn];
    const float mid = img[o];
    const float dn  = img[o + Wn];
    float vm = fmaxf(up, fmaxf(mid, dn));            // vertical 3-max at x

    float vl = __shfl_up_sync(0xffffffffu, vm, 1);   // vmax at x-1
    float vr = __shfl_down_sync(0xffffffffu, vm, 1); // vmax at x+1
    if (lane == 0) {
        vl = NEGF;
        if (wx > 0) {
            const size_t e = o - 1;
            vl = fmaxf(img[e - Wn], fmaxf(img[e], img[e + Wn]));
        }
    }
    if (lane == 31) {
        vr = NEGF;
        if (wx < WPR - 1) {
            const size_t e = o + 1;
            vr = fmaxf(img[e - Wn], fmaxf(img[e], img[e + Wn]));
        }
    }
    // mid >= vm  <=>  mid == vertical max (vm includes mid); with vl/vr: 3x3 max
    const bool cand = (mid >= 0.6f) && (mid >= vl) && (mid >= vm) && (mid >= vr)
                      && (x >= 10) && (x < Wn - 10);
    return __ballot_sync(0xffffffffu, cand);         // bit lane = x offset
}

__global__ __launch_bounds__(1024) void zf(float* __restrict__ out, int n) {
    const int i = blockIdx.x * 1024 + threadIdx.x;
    if (i < n) out[i] = 0.0f;
}

__global__ __launch_bounds__(TA) void countk(const float* __restrict__ rep) {
    const int tid  = threadIdx.x;
    const int lane = tid & 31;
    const int gr   = blockIdx.x * RPB + (tid >> 5);   // global row
    const int b = gr / Hn;
    const int y = gr % Hn;
    if (y < 10 || y >= Hn - 10) {
        if (lane == 0) g_rowcnt[gr] = 0;
        return;                                       // mask for border rows never read
    }
    const float* img = rep + (size_t)b * Hn * Wn;
    unsigned* mrow = g_mask + (size_t)gr * WPR;
    int cnt = 0;
    for (int wx = 0; wx < WPR; ++wx) {
        const unsigned word = row_word(img, y, wx, lane);
        if (lane == 0) mrow[wx] = word;
        cnt += __popc(word) & -(lane == 0);           // count once (lane 0)
    }
    if (lane == 0) g_rowcnt[gr] = cnt;
}

__global__ __launch_bounds__(1024) void scank() {
    const int tid  = threadIdx.x;
    const int lane = tid & 31;
    const int wid  = tid >> 5;
    int loc[RPT];
    int s = 0;
    #pragma unroll
    for (int i = 0; i < RPT; ++i) {                   // local exclusive prefix
        loc[i] = s;
        s += g_rowcnt[tid * RPT + i];
    }
    int v = s;                                        // inclusive warp scan of sums
    #pragma unroll
    for (int o = 1; o < 32; o <<= 1) {
        const int u = __shfl_up_sync(0xffffffffu, v, o);
        if (lane >= o) v += u;
    }
    __shared__ int ws[32];
    if (lane == 31) ws[wid] = v;
    __syncthreads();
    if (wid == 0) {                                   // scan the 32 warp totals
        int w = ws[lane];
        #pragma unroll
        for (int o = 1; o < 32; o <<= 1) {
            const int u = __shfl_up_sync(0xffffffffu, w, o);
            if (lane >= o) w += u;
        }
        ws[lane] = w;
    }
    __syncthreads();
    const int excl = (v - s) + (wid > 0 ? ws[wid - 1] : 0);
    #pragma unroll
    for (int i = 0; i < RPT; ++i)
        g_rowoff[tid * RPT + i] = excl + loc[i];
}

__global__ __launch_bounds__(TA) void emitk(float* __restrict__ out, int K) {
    const int tid  = threadIdx.x;
    const int lane = tid & 31;
    const int gr   = blockIdx.x * RPB + (tid >> 5);
    const int y = gr % Hn;
    if (y < 10 || y >= Hn - 10) return;
    const unsigned* mrow = g_mask + (size_t)gr * WPR;
    const int off = g_rowoff[gr];
    const float fy = (float)y;
    int running = 0;
    for (int wx = 0; wx < WPR; ++wx) {
        const unsigned word = mrow[wx];               // broadcast load
        if ((word >> lane) & 1u) {
            const int rank = __popc(word & ((1u << lane) - 1u));
            const int o = off + running + rank;
            if (o >= 0 && o < K) {                    // defensive: never fault
                out[o]     = fy;
                out[K + o] = (float)(wx * 32 + lane);
            }
        }
        running += __popc(word);
    }
}

extern "C" void kernel_launch(void* const* d_in, const int* in_sizes, int n_in,
                              void* d_out, int out_size) {
    const float* rep = (const float*)d_in[0];
    float* out = (float*)d_out;
    const int K = out_size / 2;
    zf<<<(out_size + 1023) / 1024, 1024>>>(out, out_size);
    countk<<<NR / RPB, TA>>>(rep);
    scank<<<1, 1024>>>();
    emitk<<<NR / RPB, TA>>>(out, K);
}

// round 10
// speedup vs baseline: 1.9919x; 1.9919x over previous
#include <cuda_runtime.h>

// NonMaxSuppression: 3x3 local max + thr 0.6 + 10px border on (16,1,1536,1536) f32.
// Output: float32 [2, K]; row 0 = y, row 1 = x, in row-major (b,y,x) nonzero order.
//
//   countk : one 384-thread block per interior row; float4 loads, separable
//            vertical max, smem horizontal exchange, shfl-packed ballot words
//            -> g_mask + per-row count.
//   scank  : chunked register scan (24 rows/thread) + warp-shuffle block scan.
//   emitk  : one warp per interior row; lanes own mask words, warp-scan popc
//            prefix, ordered bit decode. No atomics; fully deterministic.

#define Bn 16
#define Hn 1536
#define Wn 1536
#define W4 (Wn / 4)                 // 384 float4 per row
#define WPR 48                      // 32-px words per row
#define HIN (Hn - 20)               // 1516 interior rows per image
#define NRI (Bn * HIN)              // 24256 interior rows total
#define RPT 24                      // rows per scan thread (1024*24 >= NRI)
#define NEGF (-3.402823466e38f)     // -FLT_MAX; input values are in [0,1)

__device__ unsigned g_mask[(size_t)NRI * WPR];   // 4.7 MB candidate bitmask
__device__ int g_rowcnt[NRI];
__device__ int g_rowoff[NRI];

__global__ __launch_bounds__(W4) void countk(const float* __restrict__ rep) {
    const int r   = blockIdx.x;               // interior row id
    const int b   = r / HIN;
    const int y   = 10 + r % HIN;
    const int tid = threadIdx.x;
    const int lane = tid & 31;

    const float4* img = (const float4*)(rep + (size_t)b * Hn * Wn);
    const float4 ru = img[(size_t)(y - 1) * W4 + tid];
    const float4 rc = img[(size_t)y       * W4 + tid];
    const float4 rd = img[(size_t)(y + 1) * W4 + tid];

    float4 vm;                                 // vertical 3-max per pixel
    vm.x = fmaxf(ru.x, fmaxf(rc.x, rd.x));
    vm.y = fmaxf(ru.y, fmaxf(rc.y, rd.y));
    vm.z = fmaxf(ru.z, fmaxf(rc.z, rd.z));
    vm.w = fmaxf(ru.w, fmaxf(rc.w, rd.w));

    __shared__ float sX[W4];                   // vm.x (right-neighbor source)
    __shared__ float sW[W4];                   // vm.w (left-neighbor source)
    __shared__ int   swarp[W4 / 32];
    sX[tid] = vm.x;
    sW[tid] = vm.w;
    __syncthreads();
    const float left  = (tid > 0)      ? sW[tid - 1] : NEGF;
    const float right = (tid < W4 - 1) ? sX[tid + 1] : NEGF;

    const int x0 = tid * 4;
    // candidate: center >= thr and >= 3x3 max (vm includes center)
    const bool c0 = rc.x >= 0.6f && rc.x >= left && rc.x >= vm.x && rc.x >= vm.y
                    && (x0     >= 10) && (x0     < Wn - 10);
    const bool c1 = rc.y >= 0.6f && rc.y >= vm.x && rc.y >= vm.y && rc.y >= vm.z
                    && (x0 + 1 >= 10) && (x0 + 1 < Wn - 10);
    const bool c2 = rc.z >= 0.6f && rc.z >= vm.y && rc.z >= vm.z && rc.z >= vm.w
                    && (x0 + 2 >= 10) && (x0 + 2 < Wn - 10);
    const bool c3 = rc.w >= 0.6f && rc.w >= vm.z && rc.w >= vm.w && rc.w >= right
                    && (x0 + 3 >= 10) && (x0 + 3 < Wn - 10);
    const unsigned nib = (unsigned)c0 | ((unsigned)c1 << 1)
                       | ((unsigned)c2 << 2) | ((unsigned)c3 << 3);

    // assemble 32-bit word from 8 lanes x 4 bits (bit 4*(lane&7)+i = x offset)
    unsigned v = nib << (4 * (lane & 7));
    v |= __shfl_xor_sync(0xffffffffu, v, 1);
    v |= __shfl_xor_sync(0xffffffffu, v, 2);
    v |= __shfl_xor_sync(0xffffffffu, v, 4);
    if ((lane & 7) == 0)
        g_mask[(size_t)r * WPR + (tid >> 3)] = v;

    // per-row candidate count
    int cnt = __popc(nib);
    #pragma unroll
    for (int o = 16; o > 0; o >>= 1)
        cnt += __shfl_down_sync(0xffffffffu, cnt, o);
    if (lane == 0) swarp[tid >> 5] = cnt;
    __syncthreads();
    if (tid == 0) {
        int s = 0;
        #pragma unroll
        for (int i = 0; i < W4 / 32; ++i) s += swarp[i];
        g_rowcnt[r] = s;
    }
}

__global__ __launch_bounds__(1024) void scank() {
    const int tid  = threadIdx.x;
    const int lane = tid & 31;
    const int wid  = tid >> 5;
    int loc[RPT];
    int s = 0;
    #pragma unroll
    for (int i = 0; i < RPT; ++i) {                   // local exclusive prefix
        const int idx = tid * RPT + i;
        loc[i] = s;
        s += (idx < NRI) ? g_rowcnt[idx] : 0;
    }
    int v = s;                                        // inclusive warp scan of sums
    #pragma unroll
    for (int o = 1; o < 32; o <<= 1) {
        const int u = __shfl_up_sync(0xffffffffu, v, o);
        if (lane >= o) v += u;
    }
    __shared__ int ws[32];
    if (lane == 31) ws[wid] = v;
    __syncthreads();
    if (wid == 0) {                                   // scan the 32 warp totals
        int w = ws[lane];
        #pragma unroll
        for (int o = 1; o < 32; o <<= 1) {
            const int u = __shfl_up_sync(0xffffffffu, w, o);
            if (lane >= o) w += u;
        }
        ws[lane] = w;
    }
    __syncthreads();
    const int excl = (v - s) + (wid > 0 ? ws[wid - 1] : 0);
    #pragma unroll
    for (int i = 0; i < RPT; ++i) {
        const int idx = tid * RPT + i;
        if (idx < NRI) g_rowoff[idx] = excl + loc[i];
    }
}

__global__ __launch_bounds__(256) void emitk(float* __restrict__ out, int K) {
    const int tid  = threadIdx.x;
    const int lane = tid & 31;
    const int r    = blockIdx.x * 8 + (tid >> 5);     // interior row id
    const int y    = 10 + r % HIN;
    const unsigned* mrow = g_mask + (size_t)r * WPR;
    const int off = g_rowoff[r];
    const float fy = (float)y;

    // phase A: words 0..31 (one per lane)
    unsigned w = mrow[lane];
    int pc = __popc(w);
    int sc = pc;
    #pragma unroll
    for (int o = 1; o < 32; o <<= 1) {
        const int u = __shfl_up_sync(0xffffffffu, sc, o);
        if (lane >= o) sc += u;
    }
    const int totalA = __shfl_sync(0xffffffffu, sc, 31);
    int o = off + sc - pc;
    int xb = lane * 32;
    while (w) {
        const int bit = __ffs(w) - 1;
        w &= w - 1;
        if (o >= 0 && o < K) { out[o] = fy; out[K + o] = (float)(xb + bit); }
        ++o;
    }

    // phase B: words 32..47 (lanes 0..15)
    w = (lane < WPR - 32) ? mrow[32 + lane] : 0u;
    pc = __popc(w);
    sc = pc;
    #pragma unroll
    for (int o2 = 1; o2 < 32; o2 <<= 1) {
        const int u = __shfl_up_sync(0xffffffffu, sc, o2);
        if (lane >= o2) sc += u;
    }
    o = off + totalA + sc - pc;
    xb = (32 + lane) * 32;
    while (w) {
        const int bit = __ffs(w) - 1;
        w &= w - 1;
        if (o >= 0 && o < K) { out[o] = fy; out[K + o] = (float)(xb + bit); }
        ++o;
    }
}

extern "C" void kernel_launch(void* const* d_in, const int* in_sizes, int n_in,
                              void* d_out, int out_size) {
    const float* rep = (const float*)d_in[0];
    float* out = (float*)d_out;
    const int K = out_size / 2;
    countk<<<NRI, W4>>>(rep);
    scank<<<1, 1024>>>();
    emitk<<<NRI / 8, 256>>>(out, K);
}

// round 13
// speedup vs baseline: 2.4687x; 1.2393x over previous
#include <cuda_runtime.h>

// NonMaxSuppression: 3x3 local max + thr 0.6 + 10px border on (16,1,1536,1536) f32.
// Output: float32 [2, K]; row 0 = y, row 1 = x, in row-major (b,y,x) nonzero order.
//
//   countk  : 32-row strips, rolling registers (1.06x load amplification);
//             warp-per-128px segment, shfl horizontal exchange + rolling scalar
//             halo in lanes 0/31; no smem, no syncthreads. Packs candidate bits
//             -> g_mask. Border x handled by masking words 0/47.
//   rowcntk : warp per row popc over mask words -> g_rowcnt.
//   scank   : chunked register scan (24 rows/thread) + warp-shuffle block scan.
//   emitk   : warp per row; decode mask bits into smem x-list, then fully
//             coalesced ordered stores. No atomics; fully deterministic.

#define Bn 16
#define Hn 1536
#define Wn 1536
#define W4 (Wn / 4)                 // 384 float4 per row
#define WPR 48                      // 32-px words per row
#define HIN (Hn - 20)               // 1516 interior rows per image
#define NRI (Bn * HIN)              // 24256 interior rows total
#define ROWS 32                     // rows per countk strip
#define SPI ((HIN + ROWS - 1) / ROWS)   // 48 strips per image
#define RPT 24                      // rows per scan thread
#define NEGF (-3.402823466e38f)

__device__ unsigned g_mask[(size_t)NRI * WPR];   // 4.7 MB candidate bitmask
__device__ int g_rowcnt[NRI];
__device__ int g_rowoff[NRI];

__device__ __forceinline__ float fmax3(float a, float b, float c) {
    return fmaxf(a, fmaxf(b, c));
}

__global__ __launch_bounds__(384) void countk(const float* __restrict__ rep) {
    const int blk = blockIdx.x;
    const int b   = blk / SPI;
    const int s   = blk % SPI;
    const int y0  = 10 + s * ROWS;
    const int nrows = min(ROWS, (Hn - 10) - y0);
    const int tid  = threadIdx.x;
    const int lane = tid & 31;
    const int wid  = tid >> 5;

    const float* img = rep + (size_t)b * Hn * Wn;
    const float4* col = (const float4*)img;          // [y][tid] since x0/4 == tid
    const int x0 = wid * 128 + lane * 4;

    // halo column: lane 0 -> x0-1, lane 31 -> x0+4 (clamped; clamped bits are border-masked)
    const bool isEdge = (lane == 0) | (lane == 31);
    const int hx = (lane == 0) ? max(x0 - 1, 0) : min(x0 + 4, Wn - 1);

    float4 rp = col[(size_t)(y0 - 1) * W4 + tid];
    float4 rc = col[(size_t)y0       * W4 + tid];
    float hp = isEdge ? img[(size_t)(y0 - 1) * Wn + hx] : 0.0f;
    float hc = isEdge ? img[(size_t)y0       * Wn + hx] : 0.0f;

    const int gword = wid * 4 + (lane >> 3);          // global word index 0..47
    const int ridBase = b * HIN + (y0 - 10);
    const bool leader = (lane & 7) == 0;

    #pragma unroll 8
    for (int i = 0; i < nrows; ++i) {
        const int y = y0 + i;
        const float4 rn = col[(size_t)(y + 1) * W4 + tid];
        const float hn = isEdge ? img[(size_t)(y + 1) * Wn + hx] : 0.0f;

        float4 vm;                                    // vertical 3-max
        vm.x = fmax3(rp.x, rc.x, rn.x);
        vm.y = fmax3(rp.y, rc.y, rn.y);
        vm.z = fmax3(rp.z, rc.z, rn.z);
        vm.w = fmax3(rp.w, rc.w, rn.w);
        const float hvm = fmax3(hp, hc, hn);          // halo column vmax

        float left  = __shfl_up_sync(0xffffffffu, vm.w, 1);
        float right = __shfl_down_sync(0xffffffffu, vm.x, 1);
        if (lane == 0)  left  = hvm;
        if (lane == 31) right = hvm;

        // candidate: center >= thr and >= 3x3 max (vm includes center)
        const bool c0 = rc.x >= 0.6f && rc.x >= left && rc.x >= vm.x && rc.x >= vm.y;
        const bool c1 = rc.y >= 0.6f && rc.y >= vm.x && rc.y >= vm.y && rc.y >= vm.z;
        const bool c2 = rc.z >= 0.6f && rc.z >= vm.y && rc.z >= vm.z && rc.z >= vm.w;
        const bool c3 = rc.w >= 0.6f && rc.w >= vm.z && rc.w >= vm.w && rc.w >= right;
        const unsigned nib = (unsigned)c0 | ((unsigned)c1 << 1)
                           | ((unsigned)c2 << 2) | ((unsigned)c3 << 3);

        // pack 8 lanes x 4 bits -> 32-bit word (bit = x offset within word)
        unsigned v = nib << (4 * (lane & 7));
        v |= __shfl_xor_sync(0xffffffffu, v, 1);
        v |= __shfl_xor_sync(0xffffffffu, v, 2);
        v |= __shfl_xor_sync(0xffffffffu, v, 4);
        if (leader) {
            if (gword == 0)       v &= ~0x3FFu;       // x < 10
            if (gword == WPR - 1) v &= 0x003FFFFFu;   // x >= 1526
            g_mask[(size_t)(ridBase + i) * WPR + gword] = v;
        }

        rp = rc; rc = rn; hp = hc; hc = hn;
    }
}

__global__ __launch_bounds__(256) void rowcntk() {
    const int tid  = threadIdx.x;
    const int lane = tid & 31;
    const int r    = blockIdx.x * 8 + (tid >> 5);
    const unsigned* mrow = g_mask + (size_t)r * WPR;
    int c = __popc(mrow[lane]) + ((lane < WPR - 32) ? __popc(mrow[32 + lane]) : 0);
    #pragma unroll
    for (int o = 16; o > 0; o >>= 1)
        c += __shfl_down_sync(0xffffffffu, c, o);
    if (lane == 0) g_rowcnt[r] = c;
}

__global__ __launch_bounds__(1024) void scank() {
    const int tid  = threadIdx.x;
    const int lane = tid & 31;
    const int wid  = tid >> 5;
    int loc[RPT];
    int s = 0;
    #pragma unroll
    for (int i = 0; i < RPT; ++i) {
        const int idx = tid * RPT + i;
        loc[i] = s;
        s += (idx < NRI) ? g_rowcnt[idx] : 0;
    }
    int v = s;
    #pragma unroll
    for (int o = 1; o < 32; o <<= 1) {
        const int u = __shfl_up_sync(0xffffffffu, v, o);
        if (lane >= o) v += u;
    }
    __shared__ int ws[32];
    if (lane == 31) ws[wid] = v;
    __syncthreads();
    if (wid == 0) {
        int w = ws[lane];
        #pragma unroll
        for (int o = 1; o < 32; o <<= 1) {
            const int u = __shfl_up_sync(0xffffffffu, w, o);
            if (lane >= o) w += u;
        }
        ws[lane] = w;
    }
    __syncthreads();
    const int excl = (v - s) + (wid > 0 ? ws[wid - 1] : 0);
    #pragma unroll
    for (int i = 0; i < RPT; ++i) {
        const int idx = tid * RPT + i;
        if (idx < NRI) g_rowoff[idx] = excl + loc[i];
    }
}

__global__ __launch_bounds__(256) void emitk(float* __restrict__ out, int K) {
    __shared__ unsigned short sx[8][Wn];              // 24 KB: x-coords per row
    const int tid  = threadIdx.x;
    const int lane = tid & 31;
    const int wid  = tid >> 5;
    const int r    = blockIdx.x * 8 + wid;
    const int y    = 10 + r % HIN;
    const unsigned* mrow = g_mask + (size_t)r * WPR;
    const int off = g_rowoff[r];

    const unsigned wA = mrow[lane];
    const unsigned wB = (lane < WPR - 32) ? mrow[32 + lane] : 0u;
    const int pcA = __popc(wA);
    const int pcB = __popc(wB);

    int scA = pcA, scB = pcB;                         // inclusive warp scans
    #pragma unroll
    for (int o = 1; o < 32; o <<= 1) {
        const int uA = __shfl_up_sync(0xffffffffu, scA, o);
        const int uB = __shfl_up_sync(0xffffffffu, scB, o);
        if (lane >= o) { scA += uA; scB += uB; }
    }
    const int totalA = __shfl_sync(0xffffffffu, scA, 31);
    const int cnt    = totalA + __shfl_sync(0xffffffffu, scB, 31);

    // decode bits into smem x-list at ordered local offsets
    int j = scA - pcA;
    unsigned w = wA;
    int xb = lane * 32;
    while (w) {
        const int bit = __ffs(w) - 1;
        w &= w - 1;
        sx[wid][j++] = (unsigned short)(xb + bit);
    }
    j = totalA + scB - pcB;
    w = wB;
    xb = (32 + lane) * 32;
    while (w) {
        const int bit = __ffs(w) - 1;
        w &= w - 1;
        sx[wid][j++] = (unsigned short)(xb + bit);
    }
    __syncwarp();

    const float fy = (float)y;
    const int lim = min(cnt, K - off);                // defensive bound
    for (int i = lane; i < lim; i += 32) {
        out[off + i]     = fy;
        out[K + off + i] = (float)sx[wid][i];
    }
}

extern "C" void kernel_launch(void* const* d_in, const int* in_sizes, int n_in,
                              void* d_out, int out_size) {
    const float* rep = (const float*)d_in[0];
    float* out = (float*)d_out;
    const int K = out_size / 2;
    countk<<<Bn * SPI, 384>>>(rep);
    rowcntk<<<NRI / 8, 256>>>();
    scank<<<1, 1024>>>();
    emitk<<<NRI / 8, 256>>>(out, K);
}